// round 3
// baseline (speedup 1.0000x reference)
#include <cuda_runtime.h>
#include <cuda_bf16.h>

#define B_  2
#define S_  2048
#define E_  1024
#define H_  16
#define DH_ 64
#define KS_ 3

// -------- scratch (device globals; no allocations allowed) --------
__device__ float g_Q[(size_t)B_ * H_ * S_ * DH_];            // 16.8 MB
__device__ float g_K[(size_t)B_ * H_ * S_ * DH_];            // 16.8 MB
__device__ float g_V[(size_t)B_ * H_ * S_ * DH_];            // 16.8 MB
__device__ float g_attn[(size_t)B_ * S_ * E_];               // 16.8 MB
__device__ float g_scores[(size_t)B_ * H_ * S_ * S_];        // 536 MB
__device__ float g_weights[(size_t)B_ * H_ * S_ * S_];       // 536 MB

// =====================================================================
// Generic NT SGEMM: C[m,n] = alpha * sum_k A[m,k]*B[n,k] (+ bias[n])
// 128x128 block tile, TK=8, 256 threads, 8x8 micro-tile.
// mode 0: C row-major with ldc.  mode 1: split-head write for QKV:
//   m = b*S+s, n = h*DH+d -> C[((b*H+h)*S+s)*DH + d]
// =====================================================================
__global__ __launch_bounds__(256) void sgemm_nt_kernel(
    const float* __restrict__ A, const float* __restrict__ Bm,
    const float* __restrict__ bias, float* __restrict__ C,
    int K, int lda, int ldb, int ldc,
    long long strideA, long long strideB, long long strideC,
    float alpha, int mode)
{
    A  += (long long)blockIdx.z * strideA;
    Bm += (long long)blockIdx.z * strideB;
    C  += (long long)blockIdx.z * strideC;

    const int mBase = blockIdx.y * 128;
    const int nBase = blockIdx.x * 128;

    __shared__ float As[8][128];
    __shared__ float Bs[8][128];

    const int tid = threadIdx.x;
    const int ty = tid >> 4;          // 0..15
    const int tx = tid & 15;          // 0..15
    const int loadRow = tid >> 1;     // 0..127
    const int loadCol = (tid & 1) << 2;  // 0 or 4

    float acc[8][8];
#pragma unroll
    for (int i = 0; i < 8; i++)
#pragma unroll
        for (int j = 0; j < 8; j++) acc[i][j] = 0.f;

    const float* aPtr = A  + (long long)(mBase + loadRow) * lda + loadCol;
    const float* bPtr = Bm + (long long)(nBase + loadRow) * ldb + loadCol;

    for (int k0 = 0; k0 < K; k0 += 8) {
        float4 av = *(const float4*)(aPtr + k0);
        float4 bv = *(const float4*)(bPtr + k0);
        As[loadCol + 0][loadRow] = av.x;
        As[loadCol + 1][loadRow] = av.y;
        As[loadCol + 2][loadRow] = av.z;
        As[loadCol + 3][loadRow] = av.w;
        Bs[loadCol + 0][loadRow] = bv.x;
        Bs[loadCol + 1][loadRow] = bv.y;
        Bs[loadCol + 2][loadRow] = bv.z;
        Bs[loadCol + 3][loadRow] = bv.w;
        __syncthreads();
#pragma unroll
        for (int k = 0; k < 8; k++) {
            float4 a0 = *(const float4*)&As[k][ty * 8];
            float4 a1 = *(const float4*)&As[k][ty * 8 + 4];
            float4 b0 = *(const float4*)&Bs[k][tx * 8];
            float4 b1 = *(const float4*)&Bs[k][tx * 8 + 4];
            float ra[8] = {a0.x, a0.y, a0.z, a0.w, a1.x, a1.y, a1.z, a1.w};
            float rb[8] = {b0.x, b0.y, b0.z, b0.w, b1.x, b1.y, b1.z, b1.w};
#pragma unroll
            for (int i = 0; i < 8; i++)
#pragma unroll
                for (int j = 0; j < 8; j++)
                    acc[i][j] += ra[i] * rb[j];
        }
        __syncthreads();
    }

    if (mode == 0) {
#pragma unroll
        for (int i = 0; i < 8; i++) {
            const int m = mBase + ty * 8 + i;
#pragma unroll
            for (int j = 0; j < 8; j++) {
                const int n = nBase + tx * 8 + j;
                float v = alpha * acc[i][j];
                if (bias) v += bias[n];
                C[(long long)m * ldc + n] = v;
            }
        }
    } else {
#pragma unroll
        for (int i = 0; i < 8; i++) {
            const int m = mBase + ty * 8 + i;
            const int b = m >> 11;
            const int s = m & (S_ - 1);
#pragma unroll
            for (int j = 0; j < 8; j++) {
                const int n = nBase + tx * 8 + j;
                const int h = n >> 6;
                const int d = n & (DH_ - 1);
                float v = alpha * acc[i][j];
                if (bias) v += bias[n];
                C[(((long long)(b * H_ + h) * S_ + s) << 6) + d] = v;
            }
        }
    }
}

// =====================================================================
// PV GEMM (NN): out[b,q,h*64+d] = sum_k W[bh,q,k] * V[bh,k,d]
// per (b,h) batch: M=2048 (q), N=64 (d), K=2048.
// 128x64 block tile, TK=16, 256 threads, 8x4 micro-tile.
// =====================================================================
__global__ __launch_bounds__(256) void pv_kernel(
    const float* __restrict__ Wts, const float* __restrict__ V,
    float* __restrict__ out)
{
    const int bh = blockIdx.z;
    const int b = bh >> 4;
    const int h = bh & 15;
    const float* A  = Wts + (long long)bh * S_ * S_;
    const float* Bv = V   + (long long)bh * S_ * DH_;
    const int mBase = blockIdx.y * 128;

    __shared__ float As[16][128];
    __shared__ float Bs[16][64];

    const int tid = threadIdx.x;
    const int ty = tid >> 4;   // 0..15 : rows (x8)
    const int tx = tid & 15;   // 0..15 : cols (x4)

    float acc[8][4];
#pragma unroll
    for (int i = 0; i < 8; i++)
#pragma unroll
        for (int j = 0; j < 4; j++) acc[i][j] = 0.f;

    for (int k0 = 0; k0 < S_; k0 += 16) {
#pragma unroll
        for (int u = 0; u < 2; u++) {
            const int t = tid * 2 + u;       // 0..511
            const int r = t >> 2;            // 0..127
            const int c = (t & 3) * 4;       // 0,4,8,12
            float4 av = *(const float4*)(A + (long long)(mBase + r) * S_ + k0 + c);
            As[c + 0][r] = av.x;
            As[c + 1][r] = av.y;
            As[c + 2][r] = av.z;
            As[c + 3][r] = av.w;
        }
        {
            const int r = tid >> 4;          // 0..15
            const int c = (tid & 15) * 4;    // 0..60
            float4 bv = *(const float4*)(Bv + (long long)(k0 + r) * DH_ + c);
            Bs[r][c + 0] = bv.x;
            Bs[r][c + 1] = bv.y;
            Bs[r][c + 2] = bv.z;
            Bs[r][c + 3] = bv.w;
        }
        __syncthreads();
#pragma unroll
        for (int k = 0; k < 16; k++) {
            float4 a0 = *(const float4*)&As[k][ty * 8];
            float4 a1 = *(const float4*)&As[k][ty * 8 + 4];
            float4 bb = *(const float4*)&Bs[k][tx * 4];
            float ra[8] = {a0.x, a0.y, a0.z, a0.w, a1.x, a1.y, a1.z, a1.w};
            float rb[4] = {bb.x, bb.y, bb.z, bb.w};
#pragma unroll
            for (int i = 0; i < 8; i++)
#pragma unroll
                for (int j = 0; j < 4; j++)
                    acc[i][j] += ra[i] * rb[j];
        }
        __syncthreads();
    }

#pragma unroll
    for (int i = 0; i < 8; i++) {
        const int q = mBase + ty * 8 + i;
#pragma unroll
        for (int j = 0; j < 4; j++) {
            const int d = tx * 4 + j;
            out[((long long)b * S_ + q) * E_ + h * DH_ + d] = acc[i][j];
        }
    }
}

// =====================================================================
// Fused cross-head conv1d (KS=3, pad=1) + softmax over k.
// One CTA per (b,q). All 16 head score-rows (16x2048 fp32 = 128KB) in
// dynamic smem. Output heads processed in 2 register groups of 8 so each
// smem (l,c,r) triple feeds 8 output-head accumulators.
// =====================================================================
__global__ __launch_bounds__(256) void conv_softmax_kernel(
    const float* __restrict__ scores, const float* __restrict__ conv_w,
    const float* __restrict__ conv_b, float* __restrict__ weights)
{
    extern __shared__ float sm[];          // [H_][S_]
    __shared__ float cw[H_ * H_ * KS_];
    __shared__ float cb[H_];
    __shared__ float red[40];

    const int tid = threadIdx.x;
    const int bq = blockIdx.x;
    const int b = bq >> 11;
    const int q = bq & (S_ - 1);

    for (int i = tid; i < H_ * H_ * KS_; i += 256) cw[i] = conv_w[i];
    if (tid < H_) cb[tid] = conv_b[tid];

    const long long rowBase = (long long)b * H_ * S_ * S_ + (long long)q * S_;
    for (int h = 0; h < H_; h++) {
        const float4* src = (const float4*)(scores + rowBase + (long long)h * S_ * S_);
        float4* dst = (float4*)(sm + h * S_);
        for (int j = tid; j < S_ / 4; j += 256) dst[j] = src[j];
    }
    __syncthreads();

    for (int g = 0; g < 2; g++) {
        float acc[8][8];
#pragma unroll
        for (int ho = 0; ho < 8; ho++) {
            const float bias = cb[g * 8 + ho];
#pragma unroll
            for (int j = 0; j < 8; j++) acc[ho][j] = bias;
        }

        for (int hi = 0; hi < H_; hi++) {
            const float* r = sm + hi * S_;
            float l[8], c[8], rr[8];
#pragma unroll
            for (int j = 0; j < 8; j++) {
                const int k = tid + 256 * j;
                c[j]  = r[k];
                l[j]  = (k > 0)      ? r[k - 1] : 0.f;
                rr[j] = (k < S_ - 1) ? r[k + 1] : 0.f;
            }
#pragma unroll
            for (int ho = 0; ho < 8; ho++) {
                const int wi = ((g * 8 + ho) * H_ + hi) * 3;
                const float w0 = cw[wi + 0];
                const float w1 = cw[wi + 1];
                const float w2 = cw[wi + 2];
#pragma unroll
                for (int j = 0; j < 8; j++)
                    acc[ho][j] += w0 * l[j] + w1 * c[j] + w2 * rr[j];
            }
        }

        // softmax per output head in this group
        for (int hoL = 0; hoL < 8; hoL++) {
            const int ho = g * 8 + hoL;
            float m = acc[hoL][0];
#pragma unroll
            for (int j = 1; j < 8; j++) m = fmaxf(m, acc[hoL][j]);
#pragma unroll
            for (int o = 16; o > 0; o >>= 1)
                m = fmaxf(m, __shfl_xor_sync(0xffffffffu, m, o));
            __syncthreads();
            if ((tid & 31) == 0) red[tid >> 5] = m;
            __syncthreads();
            if (tid == 0) {
                float mm = red[0];
#pragma unroll
                for (int i = 1; i < 8; i++) mm = fmaxf(mm, red[i]);
                red[32] = mm;
            }
            __syncthreads();
            m = red[32];

            float s = 0.f;
            float e[8];
#pragma unroll
            for (int j = 0; j < 8; j++) {
                e[j] = __expf(acc[hoL][j] - m);
                s += e[j];
            }
#pragma unroll
            for (int o = 16; o > 0; o >>= 1)
                s += __shfl_xor_sync(0xffffffffu, s, o);
            __syncthreads();
            if ((tid & 31) == 0) red[tid >> 5] = s;
            __syncthreads();
            if (tid == 0) {
                float ss = red[0];
#pragma unroll
                for (int i = 1; i < 8; i++) ss += red[i];
                red[33] = ss;
            }
            __syncthreads();
            const float inv = 1.0f / red[33];

            float* wrow = weights + rowBase + (long long)ho * S_ * S_;
#pragma unroll
            for (int j = 0; j < 8; j++)
                wrow[tid + 256 * j] = e[j] * inv;
        }
    }
}

// =====================================================================
extern "C" void kernel_launch(void* const* d_in, const int* in_sizes, int n_in,
                              void* d_out, int out_size)
{
    const float* x  = (const float*)d_in[0];
    const float* Wq = (const float*)d_in[1];
    const float* bq = (const float*)d_in[2];
    const float* Wk = (const float*)d_in[3];
    const float* bk = (const float*)d_in[4];
    const float* Wv = (const float*)d_in[5];
    const float* bv = (const float*)d_in[6];
    const float* Wo = (const float*)d_in[7];
    const float* bo = (const float*)d_in[8];
    const float* cw = (const float*)d_in[9];
    const float* cb = (const float*)d_in[10];
    float* out = (float*)d_out;

    float *Qp, *Kp, *Vp, *Sp, *Wp, *Ap;
    cudaGetSymbolAddress((void**)&Qp, g_Q);
    cudaGetSymbolAddress((void**)&Kp, g_K);
    cudaGetSymbolAddress((void**)&Vp, g_V);
    cudaGetSymbolAddress((void**)&Sp, g_scores);
    cudaGetSymbolAddress((void**)&Wp, g_weights);
    cudaGetSymbolAddress((void**)&Ap, g_attn);

    const dim3 blk(256);

    // 1) QKV projections (split-head output layout)
    const dim3 g1(E_ / 128, (B_ * S_) / 128, 1);
    sgemm_nt_kernel<<<g1, blk>>>(x, Wq, bq, Qp, E_, E_, E_, 0, 0, 0, 0, 1.f, 1);
    sgemm_nt_kernel<<<g1, blk>>>(x, Wk, bk, Kp, E_, E_, E_, 0, 0, 0, 0, 1.f, 1);
    sgemm_nt_kernel<<<g1, blk>>>(x, Wv, bv, Vp, E_, E_, E_, 0, 0, 0, 0, 1.f, 1);

    // 2) scores = Q K^T / sqrt(DH), batched over B*H
    const dim3 g2(S_ / 128, S_ / 128, B_ * H_);
    sgemm_nt_kernel<<<g2, blk>>>(Qp, Kp, nullptr, Sp, DH_, DH_, DH_, S_,
                                 (long long)S_ * DH_, (long long)S_ * DH_,
                                 (long long)S_ * S_, 0.125f, 0);

    // 3) cross-head conv + softmax
    const int convSmem = H_ * S_ * (int)sizeof(float);  // 128 KB
    cudaFuncSetAttribute(conv_softmax_kernel,
                         cudaFuncAttributeMaxDynamicSharedMemorySize, convSmem);
    conv_softmax_kernel<<<B_ * S_, blk, convSmem>>>(Sp, cw, cb, Wp);

    // 4) PV, merged-head layout [B,S,E]
    const dim3 g3(1, S_ / 128, B_ * H_);
    pv_kernel<<<g3, blk>>>(Wp, Vp, Ap);

    // 5) output projection
    sgemm_nt_kernel<<<g1, blk>>>(Ap, Wo, bo, out, E_, E_, E_, E_, 0, 0, 0, 1.f, 0);
}

// round 6
// speedup vs baseline: 1.3949x; 1.3949x over previous
#include <cuda_runtime.h>
#include <cuda_bf16.h>

#define B_  2
#define S_  2048
#define E_  1024
#define H_  16
#define DH_ 64
#define KS_ 3

// -------- scratch (device globals; no allocations allowed) --------
__device__ float g_Q[(size_t)B_ * H_ * S_ * DH_];            // 16.8 MB
__device__ float g_K[(size_t)B_ * H_ * S_ * DH_];            // 16.8 MB
__device__ float g_V[(size_t)B_ * H_ * S_ * DH_];            // 16.8 MB
__device__ float g_attn[(size_t)B_ * S_ * E_];               // 16.8 MB
__device__ float g_scores[(size_t)B_ * H_ * S_ * S_];        // 536 MB
__device__ float g_weights[(size_t)B_ * H_ * S_ * S_];       // 536 MB

__device__ __forceinline__ unsigned f2tf32(float f) {
    unsigned u;
    asm("cvt.rna.tf32.f32 %0, %1;" : "=r"(u) : "f"(f));
    return u;
}

__device__ __forceinline__ void mma_tf32(float c[4], const unsigned a[4],
                                         unsigned b0, unsigned b1) {
    asm volatile(
        "mma.sync.aligned.m16n8k8.row.col.f32.tf32.tf32.f32 "
        "{%0,%1,%2,%3}, {%4,%5,%6,%7}, {%8,%9}, {%0,%1,%2,%3};"
        : "+f"(c[0]), "+f"(c[1]), "+f"(c[2]), "+f"(c[3])
        : "r"(a[0]), "r"(a[1]), "r"(a[2]), "r"(a[3]), "r"(b0), "r"(b1));
}

// =====================================================================
// TF32 tensor-core GEMM: C[m,n] = alpha * sum_k A[m,k]*B'[k,n] (+bias[n])
//   BT=true : B global layout [n][k] (NT gemm — projections, QK^T)
//   BT=false: B global layout [k][n] (NN gemm — PV), requires BN==64
// BM=128, BK=16, 256 threads, 8 warps as 2(m) x 4(n); warp tile 64 x BN/4.
// mode 0: C[m*ldc+n]     mode 1: QKV split-head write
// mode 2: PV merged-head write: C pre-offset by (b,h), ldc = E_
// =====================================================================
template<int BN, bool BT>
__global__ __launch_bounds__(256) void tf32_gemm_kernel(
    const float* __restrict__ A, const float* __restrict__ Bm,
    const float* __restrict__ bias, float* __restrict__ C,
    int K, int lda, int ldb, int ldc,
    long long sA, long long sB, long long sC,
    float alpha, int mode)
{
    constexpr int WN = BN / 4;       // warp n extent
    constexpr int NT = WN / 8;       // n mma tiles per warp (4 or 2)
    constexpr int APAD = 8;          // row stride 136 / 72 : ≡8 mod 32 -> conflict-free

    const int z = blockIdx.z;
    A  += (long long)z * sA;
    Bm += (long long)z * sB;
    if (mode == 2) C += ((long long)(z >> 4)) * S_ * E_ + (long long)(z & 15) * DH_;
    else           C += (long long)z * sC;

    const int mBase = blockIdx.y * 128;
    const int nBase = blockIdx.x * BN;

    __shared__ unsigned As[16][128 + APAD];
    __shared__ unsigned Bs[16][BN + APAD];

    const int tid  = threadIdx.x;
    const int lane = tid & 31;
    const int gid  = lane >> 2;      // 0..7
    const int tig  = lane & 3;       // 0..3
    const int warpId = tid >> 5;     // 0..7
    const int wm = (warpId & 1) * 64;
    const int wn = (warpId >> 1) * WN;

    float acc[4][NT][4];
#pragma unroll
    for (int i = 0; i < 4; i++)
#pragma unroll
        for (int j = 0; j < NT; j++)
#pragma unroll
            for (int r = 0; r < 4; r++) acc[i][j][r] = 0.f;

    // global->smem load assignments
    const int aRow = tid & 127;
    const int aK = (tid >> 7) << 3;            // 0 or 8
    const float* aPtr = A + (long long)(mBase + aRow) * lda + aK;

    const float* bPtr;
    int bRow = 0, bK = 0, bN = 0;
    if (BT) {               // B [n][k]; tile BN x 16 (BN==128 here)
        bRow = tid & 127;
        bK = (tid >> 7) << 3;
        bPtr = Bm + (long long)(nBase + bRow) * ldb + bK;
    } else {                // B [k][n]; tile 16 x BN (BN==64 here)
        bK = tid >> 4;                  // 0..15
        bN = (tid & 15) << 2;           // 0..60
        bPtr = Bm + (long long)bK * ldb + nBase + bN;
    }

    for (int k0 = 0; k0 < K; k0 += 16) {
        // A tile (transpose to [k][m])
        {
            float4 v0 = *(const float4*)(aPtr + k0);
            float4 v1 = *(const float4*)(aPtr + k0 + 4);
            As[aK + 0][aRow] = f2tf32(v0.x);
            As[aK + 1][aRow] = f2tf32(v0.y);
            As[aK + 2][aRow] = f2tf32(v0.z);
            As[aK + 3][aRow] = f2tf32(v0.w);
            As[aK + 4][aRow] = f2tf32(v1.x);
            As[aK + 5][aRow] = f2tf32(v1.y);
            As[aK + 6][aRow] = f2tf32(v1.z);
            As[aK + 7][aRow] = f2tf32(v1.w);
        }
        // B tile
        if (BT) {
            float4 v0 = *(const float4*)(bPtr + k0);
            float4 v1 = *(const float4*)(bPtr + k0 + 4);
            Bs[bK + 0][bRow] = f2tf32(v0.x);
            Bs[bK + 1][bRow] = f2tf32(v0.y);
            Bs[bK + 2][bRow] = f2tf32(v0.z);
            Bs[bK + 3][bRow] = f2tf32(v0.w);
            Bs[bK + 4][bRow] = f2tf32(v1.x);
            Bs[bK + 5][bRow] = f2tf32(v1.y);
            Bs[bK + 6][bRow] = f2tf32(v1.z);
            Bs[bK + 7][bRow] = f2tf32(v1.w);
        } else {
            float4 v = *(const float4*)(bPtr + (long long)k0 * ldb);
            Bs[bK][bN + 0] = f2tf32(v.x);
            Bs[bK][bN + 1] = f2tf32(v.y);
            Bs[bK][bN + 2] = f2tf32(v.z);
            Bs[bK][bN + 3] = f2tf32(v.w);
        }
        __syncthreads();

#pragma unroll
        for (int kk = 0; kk < 2; kk++) {
            const int ks = kk * 8;
            unsigned af[4][4];
#pragma unroll
            for (int im = 0; im < 4; im++) {
                const int m = wm + im * 16 + gid;
                af[im][0] = As[ks + tig][m];
                af[im][1] = As[ks + tig][m + 8];
                af[im][2] = As[ks + tig + 4][m];
                af[im][3] = As[ks + tig + 4][m + 8];
            }
            unsigned bf[NT][2];
#pragma unroll
            for (int in = 0; in < NT; in++) {
                const int n = wn + in * 8 + gid;
                bf[in][0] = Bs[ks + tig][n];
                bf[in][1] = Bs[ks + tig + 4][n];
            }
#pragma unroll
            for (int im = 0; im < 4; im++)
#pragma unroll
                for (int in = 0; in < NT; in++)
                    mma_tf32(acc[im][in], af[im], bf[in][0], bf[in][1]);
        }
        __syncthreads();
    }

    // epilogue
#pragma unroll
    for (int im = 0; im < 4; im++) {
#pragma unroll
        for (int in = 0; in < NT; in++) {
#pragma unroll
            for (int r = 0; r < 4; r++) {
                const int m = mBase + wm + im * 16 + gid + ((r >> 1) << 3);
                const int n = nBase + wn + in * 8 + 2 * tig + (r & 1);
                float v = alpha * acc[im][in][r];
                if (bias) v += bias[n];
                if (mode == 1) {
                    const int b = m >> 11;
                    const int s = m & (S_ - 1);
                    const int h = n >> 6;
                    const int d = n & (DH_ - 1);
                    C[(((long long)(b * H_ + h) * S_ + s) << 6) + d] = v;
                } else {
                    C[(long long)m * ldc + n] = v;
                }
            }
        }
    }
}

// =====================================================================
// Fused cross-head conv1d (KS=3, pad=1) + softmax over k.
// One CTA per (b,q). All 16 head score-rows in 128KB dynamic smem.
// =====================================================================
__global__ __launch_bounds__(256) void conv_softmax_kernel(
    const float* __restrict__ scores, const float* __restrict__ conv_w,
    const float* __restrict__ conv_b, float* __restrict__ weights)
{
    extern __shared__ float sm[];          // [H_][S_]
    __shared__ float cw[H_ * H_ * KS_];
    __shared__ float cb[H_];
    __shared__ float red[40];

    const int tid = threadIdx.x;
    const int bq = blockIdx.x;
    const int b = bq >> 11;
    const int q = bq & (S_ - 1);

    for (int i = tid; i < H_ * H_ * KS_; i += 256) cw[i] = conv_w[i];
    if (tid < H_) cb[tid] = conv_b[tid];

    const long long rowBase = (long long)b * H_ * S_ * S_ + (long long)q * S_;
    for (int h = 0; h < H_; h++) {
        const float4* src = (const float4*)(scores + rowBase + (long long)h * S_ * S_);
        float4* dst = (float4*)(sm + h * S_);
        for (int j = tid; j < S_ / 4; j += 256) dst[j] = src[j];
    }
    __syncthreads();

    for (int g = 0; g < 2; g++) {
        float acc[8][8];
#pragma unroll
        for (int ho = 0; ho < 8; ho++) {
            const float bias = cb[g * 8 + ho];
#pragma unroll
            for (int j = 0; j < 8; j++) acc[ho][j] = bias;
        }

        for (int hi = 0; hi < H_; hi++) {
            const float* r = sm + hi * S_;
            float l[8], c[8], rr[8];
#pragma unroll
            for (int j = 0; j < 8; j++) {
                const int k = tid + 256 * j;
                c[j]  = r[k];
                l[j]  = (k > 0)      ? r[k - 1] : 0.f;
                rr[j] = (k < S_ - 1) ? r[k + 1] : 0.f;
            }
#pragma unroll
            for (int ho = 0; ho < 8; ho++) {
                const int wi = ((g * 8 + ho) * H_ + hi) * 3;
                const float w0 = cw[wi + 0];
                const float w1 = cw[wi + 1];
                const float w2 = cw[wi + 2];
#pragma unroll
                for (int j = 0; j < 8; j++)
                    acc[ho][j] += w0 * l[j] + w1 * c[j] + w2 * rr[j];
            }
        }

        for (int hoL = 0; hoL < 8; hoL++) {
            const int ho = g * 8 + hoL;
            float m = acc[hoL][0];
#pragma unroll
            for (int j = 1; j < 8; j++) m = fmaxf(m, acc[hoL][j]);
#pragma unroll
            for (int o = 16; o > 0; o >>= 1)
                m = fmaxf(m, __shfl_xor_sync(0xffffffffu, m, o));
            __syncthreads();
            if ((tid & 31) == 0) red[tid >> 5] = m;
            __syncthreads();
            if (tid == 0) {
                float mm = red[0];
#pragma unroll
                for (int i = 1; i < 8; i++) mm = fmaxf(mm, red[i]);
                red[32] = mm;
            }
            __syncthreads();
            m = red[32];

            float s = 0.f;
            float e[8];
#pragma unroll
            for (int j = 0; j < 8; j++) {
                e[j] = __expf(acc[hoL][j] - m);
                s += e[j];
            }
#pragma unroll
            for (int o = 16; o > 0; o >>= 1)
                s += __shfl_xor_sync(0xffffffffu, s, o);
            __syncthreads();
            if ((tid & 31) == 0) red[tid >> 5] = s;
            __syncthreads();
            if (tid == 0) {
                float ss = red[0];
#pragma unroll
                for (int i = 1; i < 8; i++) ss += red[i];
                red[33] = ss;
            }
            __syncthreads();
            const float inv = 1.0f / red[33];

            float* wrow = weights + rowBase + (long long)ho * S_ * S_;
#pragma unroll
            for (int j = 0; j < 8; j++)
                wrow[tid + 256 * j] = e[j] * inv;
        }
    }
}

// =====================================================================
extern "C" void kernel_launch(void* const* d_in, const int* in_sizes, int n_in,
                              void* d_out, int out_size)
{
    const float* x  = (const float*)d_in[0];
    const float* Wq = (const float*)d_in[1];
    const float* bq = (const float*)d_in[2];
    const float* Wk = (const float*)d_in[3];
    const float* bk = (const float*)d_in[4];
    const float* Wv = (const float*)d_in[5];
    const float* bv = (const float*)d_in[6];
    const float* Wo = (const float*)d_in[7];
    const float* bo = (const float*)d_in[8];
    const float* cw = (const float*)d_in[9];
    const float* cb = (const float*)d_in[10];
    float* out = (float*)d_out;

    float *Qp, *Kp, *Vp, *Sp, *Wp, *Ap;
    cudaGetSymbolAddress((void**)&Qp, g_Q);
    cudaGetSymbolAddress((void**)&Kp, g_K);
    cudaGetSymbolAddress((void**)&Vp, g_V);
    cudaGetSymbolAddress((void**)&Sp, g_scores);
    cudaGetSymbolAddress((void**)&Wp, g_weights);
    cudaGetSymbolAddress((void**)&Ap, g_attn);

    const dim3 blk(256);

    // 1) QKV projections (tf32 MMA, split-head output)
    const dim3 g1(E_ / 128, (B_ * S_) / 128, 1);
    tf32_gemm_kernel<128, true><<<g1, blk>>>(x, Wq, bq, Qp, E_, E_, E_, 0, 0, 0, 0, 1.f, 1);
    tf32_gemm_kernel<128, true><<<g1, blk>>>(x, Wk, bk, Kp, E_, E_, E_, 0, 0, 0, 0, 1.f, 1);
    tf32_gemm_kernel<128, true><<<g1, blk>>>(x, Wv, bv, Vp, E_, E_, E_, 0, 0, 0, 0, 1.f, 1);

    // 2) scores = Q K^T / sqrt(DH), batched over B*H
    const dim3 g2(S_ / 128, S_ / 128, B_ * H_);
    tf32_gemm_kernel<128, true><<<g2, blk>>>(Qp, Kp, nullptr, Sp, DH_, DH_, DH_, S_,
                                             (long long)S_ * DH_, (long long)S_ * DH_,
                                             (long long)S_ * S_, 0.125f, 0);

    // 3) cross-head conv + softmax
    const int convSmem = H_ * S_ * (int)sizeof(float);  // 128 KB
    cudaFuncSetAttribute(conv_softmax_kernel,
                         cudaFuncAttributeMaxDynamicSharedMemorySize, convSmem);
    conv_softmax_kernel<<<B_ * S_, blk, convSmem>>>(Sp, cw, cb, Wp);

    // 4) PV (NN tf32 MMA), merged-head layout [B,S,E]
    const dim3 g3(1, S_ / 128, B_ * H_);
    tf32_gemm_kernel<64, false><<<g3, blk>>>(Wp, Vp, nullptr, Ap, S_, S_, DH_, E_,
                                             (long long)S_ * S_, (long long)S_ * DH_,
                                             0, 1.f, 2);

    // 5) output projection
    tf32_gemm_kernel<128, true><<<g1, blk>>>(Ap, Wo, bo, out, E_, E_, E_, E_, 0, 0, 0, 1.f, 0);
}

// round 10
// speedup vs baseline: 1.4027x; 1.0056x over previous
#include <cuda_runtime.h>
#include <cuda_bf16.h>

#define B_  2
#define S_  2048
#define E_  1024
#define H_  16
#define DH_ 64
#define KS_ 3

// -------- scratch (device globals; no allocations allowed) --------
__device__ float g_Q[(size_t)B_ * H_ * S_ * DH_];            // 16.8 MB
__device__ float g_K[(size_t)B_ * H_ * S_ * DH_];            // 16.8 MB
__device__ float g_V[(size_t)B_ * H_ * S_ * DH_];            // 16.8 MB
__device__ float g_attn[(size_t)B_ * S_ * E_];               // 16.8 MB
__device__ float g_scores[(size_t)B_ * H_ * S_ * S_];        // 536 MB
__device__ float g_weights[(size_t)B_ * H_ * S_ * S_];       // 536 MB

__device__ __forceinline__ unsigned f2tf32(float f) {
    unsigned u;
    asm("cvt.rna.tf32.f32 %0, %1;" : "=r"(u) : "f"(f));
    return u;
}

__device__ __forceinline__ void mma_tf32(float c[4], const unsigned a[4],
                                         unsigned b0, unsigned b1) {
    asm volatile(
        "mma.sync.aligned.m16n8k8.row.col.f32.tf32.tf32.f32 "
        "{%0,%1,%2,%3}, {%4,%5,%6,%7}, {%8,%9}, {%0,%1,%2,%3};"
        : "+f"(c[0]), "+f"(c[1]), "+f"(c[2]), "+f"(c[3])
        : "r"(a[0]), "r"(a[1]), "r"(a[2]), "r"(a[3]), "r"(b0), "r"(b1));
}

// =====================================================================
// TF32 tensor-core GEMM: C[m,n] = alpha * sum_k A[m,k]*B'[k,n] (+bias[n])
//   BT=true : B global layout [n][k] (NT gemm — projections, QK^T)
//   BT=false: B global layout [k][n] (NN gemm — PV), requires BN==64
// BM=128, BK=16, 256 threads, 8 warps as 2(m) x 4(n); warp tile 64 x BN/4.
// mode 0: C[m*ldc+n]     mode 1: QKV split-head write
// mode 2: PV merged-head write: C pre-offset by (b,h), ldc = E_
// =====================================================================
template<int BN, bool BT>
__global__ __launch_bounds__(256) void tf32_gemm_kernel(
    const float* __restrict__ A, const float* __restrict__ Bm,
    const float* __restrict__ bias, float* __restrict__ C,
    int K, int lda, int ldb, int ldc,
    long long sA, long long sB, long long sC,
    float alpha, int mode)
{
    constexpr int WN = BN / 4;       // warp n extent
    constexpr int NT = WN / 8;       // n mma tiles per warp (4 or 2)
    constexpr int APAD = 8;          // row stride 136 / 72 : ≡8 mod 32 -> conflict-free

    const int z = blockIdx.z;
    A  += (long long)z * sA;
    Bm += (long long)z * sB;
    if (mode == 2) C += ((long long)(z >> 4)) * S_ * E_ + (long long)(z & 15) * DH_;
    else           C += (long long)z * sC;

    const int mBase = blockIdx.y * 128;
    const int nBase = blockIdx.x * BN;

    __shared__ unsigned As[16][128 + APAD];
    __shared__ unsigned Bs[16][BN + APAD];

    const int tid  = threadIdx.x;
    const int lane = tid & 31;
    const int gid  = lane >> 2;      // 0..7
    const int tig  = lane & 3;       // 0..3
    const int warpId = tid >> 5;     // 0..7
    const int wm = (warpId & 1) * 64;
    const int wn = (warpId >> 1) * WN;

    float acc[4][NT][4];
#pragma unroll
    for (int i = 0; i < 4; i++)
#pragma unroll
        for (int j = 0; j < NT; j++)
#pragma unroll
            for (int r = 0; r < 4; r++) acc[i][j][r] = 0.f;

    // global->smem load assignments
    const int aRow = tid & 127;
    const int aK = (tid >> 7) << 3;            // 0 or 8
    const float* aPtr = A + (long long)(mBase + aRow) * lda + aK;

    const float* bPtr;
    int bRow = 0, bK = 0, bN = 0;
    if (BT) {               // B [n][k]; tile BN x 16 (BN==128 here)
        bRow = tid & 127;
        bK = (tid >> 7) << 3;
        bPtr = Bm + (long long)(nBase + bRow) * ldb + bK;
    } else {                // B [k][n]; tile 16 x BN (BN==64 here)
        bK = tid >> 4;                  // 0..15
        bN = (tid & 15) << 2;           // 0..60
        bPtr = Bm + (long long)bK * ldb + nBase + bN;
    }

    for (int k0 = 0; k0 < K; k0 += 16) {
        // A tile (transpose to [k][m])
        {
            float4 v0 = *(const float4*)(aPtr + k0);
            float4 v1 = *(const float4*)(aPtr + k0 + 4);
            As[aK + 0][aRow] = f2tf32(v0.x);
            As[aK + 1][aRow] = f2tf32(v0.y);
            As[aK + 2][aRow] = f2tf32(v0.z);
            As[aK + 3][aRow] = f2tf32(v0.w);
            As[aK + 4][aRow] = f2tf32(v1.x);
            As[aK + 5][aRow] = f2tf32(v1.y);
            As[aK + 6][aRow] = f2tf32(v1.z);
            As[aK + 7][aRow] = f2tf32(v1.w);
        }
        // B tile
        if (BT) {
            float4 v0 = *(const float4*)(bPtr + k0);
            float4 v1 = *(const float4*)(bPtr + k0 + 4);
            Bs[bK + 0][bRow] = f2tf32(v0.x);
            Bs[bK + 1][bRow] = f2tf32(v0.y);
            Bs[bK + 2][bRow] = f2tf32(v0.z);
            Bs[bK + 3][bRow] = f2tf32(v0.w);
            Bs[bK + 4][bRow] = f2tf32(v1.x);
            Bs[bK + 5][bRow] = f2tf32(v1.y);
            Bs[bK + 6][bRow] = f2tf32(v1.z);
            Bs[bK + 7][bRow] = f2tf32(v1.w);
        } else {
            float4 v = *(const float4*)(bPtr + (long long)k0 * ldb);
            Bs[bK][bN + 0] = f2tf32(v.x);
            Bs[bK][bN + 1] = f2tf32(v.y);
            Bs[bK][bN + 2] = f2tf32(v.z);
            Bs[bK][bN + 3] = f2tf32(v.w);
        }
        __syncthreads();

#pragma unroll
        for (int kk = 0; kk < 2; kk++) {
            const int ks = kk * 8;
            unsigned af[4][4];
#pragma unroll
            for (int im = 0; im < 4; im++) {
                const int m = wm + im * 16 + gid;
                af[im][0] = As[ks + tig][m];
                af[im][1] = As[ks + tig][m + 8];
                af[im][2] = As[ks + tig + 4][m];
                af[im][3] = As[ks + tig + 4][m + 8];
            }
            unsigned bf[NT][2];
#pragma unroll
            for (int in = 0; in < NT; in++) {
                const int n = wn + in * 8 + gid;
                bf[in][0] = Bs[ks + tig][n];
                bf[in][1] = Bs[ks + tig + 4][n];
            }
#pragma unroll
            for (int im = 0; im < 4; im++)
#pragma unroll
                for (int in = 0; in < NT; in++)
                    mma_tf32(acc[im][in], af[im], bf[in][0], bf[in][1]);
        }
        __syncthreads();
    }

    // epilogue
#pragma unroll
    for (int im = 0; im < 4; im++) {
#pragma unroll
        for (int in = 0; in < NT; in++) {
#pragma unroll
            for (int r = 0; r < 4; r++) {
                const int m = mBase + wm + im * 16 + gid + ((r >> 1) << 3);
                const int n = nBase + wn + in * 8 + 2 * tig + (r & 1);
                float v = alpha * acc[im][in][r];
                if (bias) v += bias[n];
                if (mode == 1) {
                    const int b = m >> 11;
                    const int s = m & (S_ - 1);
                    const int h = n >> 6;
                    const int d = n & (DH_ - 1);
                    C[(((long long)(b * H_ + h) * S_ + s) << 6) + d] = v;
                } else {
                    C[(long long)m * ldc + n] = v;
                }
            }
        }
    }
}

// =====================================================================
// Fused cross-head conv1d (KS=3, pad=1) + softmax over k.
// One CTA per (b,q). All 16 head score-rows in 128KB dynamic smem.
// =====================================================================
__global__ __launch_bounds__(256) void conv_softmax_kernel(
    const float* __restrict__ scores, const float* __restrict__ conv_w,
    const float* __restrict__ conv_b, float* __restrict__ weights)
{
    extern __shared__ float sm[];          // [H_][S_]
    __shared__ float cw[H_ * H_ * KS_];
    __shared__ float cb[H_];
    __shared__ float red[40];

    const int tid = threadIdx.x;
    const int bq = blockIdx.x;
    const int b = bq >> 11;
    const int q = bq & (S_ - 1);

    for (int i = tid; i < H_ * H_ * KS_; i += 256) cw[i] = conv_w[i];
    if (tid < H_) cb[tid] = conv_b[tid];

    const long long rowBase = (long long)b * H_ * S_ * S_ + (long long)q * S_;
    for (int h = 0; h < H_; h++) {
        const float4* src = (const float4*)(scores + rowBase + (long long)h * S_ * S_);
        float4* dst = (float4*)(sm + h * S_);
        for (int j = tid; j < S_ / 4; j += 256) dst[j] = src[j];
    }
    __syncthreads();

    for (int g = 0; g < 2; g++) {
        float acc[8][8];
#pragma unroll
        for (int ho = 0; ho < 8; ho++) {
            const float bias = cb[g * 8 + ho];
#pragma unroll
            for (int j = 0; j < 8; j++) acc[ho][j] = bias;
        }

        for (int hi = 0; hi < H_; hi++) {
            const float* r = sm + hi * S_;
            float l[8], c[8], rr[8];
#pragma unroll
            for (int j = 0; j < 8; j++) {
                const int k = tid + 256 * j;
                c[j]  = r[k];
                l[j]  = (k > 0)      ? r[k - 1] : 0.f;
                rr[j] = (k < S_ - 1) ? r[k + 1] : 0.f;
            }
#pragma unroll
            for (int ho = 0; ho < 8; ho++) {
                const int wi = ((g * 8 + ho) * H_ + hi) * 3;
                const float w0 = cw[wi + 0];
                const float w1 = cw[wi + 1];
                const float w2 = cw[wi + 2];
#pragma unroll
                for (int j = 0; j < 8; j++)
                    acc[ho][j] += w0 * l[j] + w1 * c[j] + w2 * rr[j];
            }
        }

        for (int hoL = 0; hoL < 8; hoL++) {
            const int ho = g * 8 + hoL;
            float m = acc[hoL][0];
#pragma unroll
            for (int j = 1; j < 8; j++) m = fmaxf(m, acc[hoL][j]);
#pragma unroll
            for (int o = 16; o > 0; o >>= 1)
                m = fmaxf(m, __shfl_xor_sync(0xffffffffu, m, o));
            __syncthreads();
            if ((tid & 31) == 0) red[tid >> 5] = m;
            __syncthreads();
            if (tid == 0) {
                float mm = red[0];
#pragma unroll
                for (int i = 1; i < 8; i++) mm = fmaxf(mm, red[i]);
                red[32] = mm;
            }
            __syncthreads();
            m = red[32];

            float s = 0.f;
            float e[8];
#pragma unroll
            for (int j = 0; j < 8; j++) {
                e[j] = __expf(acc[hoL][j] - m);
                s += e[j];
            }
#pragma unroll
            for (int o = 16; o > 0; o >>= 1)
                s += __shfl_xor_sync(0xffffffffu, s, o);
            __syncthreads();
            if ((tid & 31) == 0) red[tid >> 5] = s;
            __syncthreads();
            if (tid == 0) {
                float ss = red[0];
#pragma unroll
                for (int i = 1; i < 8; i++) ss += red[i];
                red[33] = ss;
            }
            __syncthreads();
            const float inv = 1.0f / red[33];

            float* wrow = weights + rowBase + (long long)ho * S_ * S_;
#pragma unroll
            for (int j = 0; j < 8; j++)
                wrow[tid + 256 * j] = e[j] * inv;
        }
    }
}

// =====================================================================
extern "C" void kernel_launch(void* const* d_in, const int* in_sizes, int n_in,
                              void* d_out, int out_size)
{
    const float* x  = (const float*)d_in[0];
    const float* Wq = (const float*)d_in[1];
    const float* bq = (const float*)d_in[2];
    const float* Wk = (const float*)d_in[3];
    const float* bk = (const float*)d_in[4];
    const float* Wv = (const float*)d_in[5];
    const float* bv = (const float*)d_in[6];
    const float* Wo = (const float*)d_in[7];
    const float* bo = (const float*)d_in[8];
    const float* cw = (const float*)d_in[9];
    const float* cb = (const float*)d_in[10];
    float* out = (float*)d_out;

    float *Qp, *Kp, *Vp, *Sp, *Wp, *Ap;
    cudaGetSymbolAddress((void**)&Qp, g_Q);
    cudaGetSymbolAddress((void**)&Kp, g_K);
    cudaGetSymbolAddress((void**)&Vp, g_V);
    cudaGetSymbolAddress((void**)&Sp, g_scores);
    cudaGetSymbolAddress((void**)&Wp, g_weights);
    cudaGetSymbolAddress((void**)&Ap, g_attn);

    const dim3 blk(256);

    // 1) QKV projections (tf32 MMA, split-head output)
    const dim3 g1(E_ / 128, (B_ * S_) / 128, 1);
    tf32_gemm_kernel<128, true><<<g1, blk>>>(x, Wq, bq, Qp, E_, E_, E_, 0, 0, 0, 0, 1.f, 1);
    tf32_gemm_kernel<128, true><<<g1, blk>>>(x, Wk, bk, Kp, E_, E_, E_, 0, 0, 0, 0, 1.f, 1);
    tf32_gemm_kernel<128, true><<<g1, blk>>>(x, Wv, bv, Vp, E_, E_, E_, 0, 0, 0, 0, 1.f, 1);

    // 2) scores = Q K^T / sqrt(DH), batched over B*H
    const dim3 g2(S_ / 128, S_ / 128, B_ * H_);
    tf32_gemm_kernel<128, true><<<g2, blk>>>(Qp, Kp, nullptr, Sp, DH_, DH_, DH_, S_,
                                             (long long)S_ * DH_, (long long)S_ * DH_,
                                             (long long)S_ * S_, 0.125f, 0);

    // 3) cross-head conv + softmax
    const int convSmem = H_ * S_ * (int)sizeof(float);  // 128 KB
    cudaFuncSetAttribute(conv_softmax_kernel,
                         cudaFuncAttributeMaxDynamicSharedMemorySize, convSmem);
    conv_softmax_kernel<<<B_ * S_, blk, convSmem>>>(Sp, cw, cb, Wp);

    // 4) PV (NN tf32 MMA), merged-head layout [B,S,E]
    const dim3 g3(1, S_ / 128, B_ * H_);
    tf32_gemm_kernel<64, false><<<g3, blk>>>(Wp, Vp, nullptr, Ap, S_, S_, DH_, E_,
                                             (long long)S_ * S_, (long long)S_ * DH_,
                                             0, 1.f, 2);

    // 5) output projection
    tf32_gemm_kernel<128, true><<<g1, blk>>>(Ap, Wo, bo, out, E_, E_, E_, E_, 0, 0, 0, 1.f, 0);
}